// round 10
// baseline (speedup 1.0000x reference)
#include <cuda_runtime.h>
#include <cuda_bf16.h>

// CensoredLoss: outputs [B, T, V-1] f32, targets [B, T, V] f32, T=512, V=5.
// loss  = sum_{b,t} [ tgt0*log(1 - sum(out) + EPS) + sum_v tgt_{v+1}*log(out_v + EPS) ]
//         (masked rows have all-zero targets -> contribute exactly 0)
// count = #{(b,t) : sum_v targets[b,t,v] > 0}   (valid prefix => sum of lengths)
// result = count > 0 ? -loss/count : 0
//
// SINGLE kernel. Per-block: 4 rows, smem-staged targets, one block reduction,
// fire-and-forget RED atomics. Thread 0 then increments a ticket with
// atom.acq_rel.gpu (release publishes this block's REDs; the acquire on the
// final increment makes ALL blocks' REDs visible). The last block writes the
// scalar and resets the accumulators for the next graph replay. No fence, no
// trailing block-wide sync, no finalize kernel node (~5.5us saved).

#define T_DIM 512
#define V_DIM 5
#define RPB   4                       // rows per block
#define ROW_FLOATS (T_DIM * V_DIM)    // 2560
#define EPSF  1e-8f
#define NTHREADS 512

__device__ double       g_loss;       // zero at module load; last block re-zeros
__device__ unsigned int g_count;
__device__ unsigned int g_ticket;

__global__ __launch_bounds__(NTHREADS, 4)
void cl_main_kernel(const float* __restrict__ outputs,
                    const float* __restrict__ targets,
                    float* __restrict__ out,
                    int nblocks)
{
    __shared__ float s_tgt[RPB * ROW_FLOATS];      // 40960 B, four rows of targets
    __shared__ float s_sum[NTHREADS / 32];
    __shared__ int   s_cnt[NTHREADS / 32];

    const int b0  = blockIdx.x * RPB;
    const int tid = threadIdx.x;
    const int t   = tid;                            // one timestep per thread per row

    // Prefetch all four rows' outputs records (float4, 16B aligned) first so
    // their DRAM latency overlaps the targets staging.
    const float4* og4 = reinterpret_cast<const float4*>(outputs);
    const float4 o0 = og4[(size_t)(b0 + 0) * T_DIM + t];
    const float4 o1 = og4[(size_t)(b0 + 1) * T_DIM + t];
    const float4 o2 = og4[(size_t)(b0 + 2) * T_DIM + t];
    const float4 o3 = og4[(size_t)(b0 + 3) * T_DIM + t];

    // Stage 4 rows of targets via fully-coalesced float4 loads (rows adjacent;
    // block base = b0 * 2560 floats = b0 * 10240 B -> 16B aligned).
    const float4* tg4 = reinterpret_cast<const float4*>(
        targets + (size_t)b0 * ROW_FLOATS);
    float4* s4 = reinterpret_cast<float4*>(s_tgt);
    #pragma unroll
    for (int i = tid; i < (RPB * ROW_FLOATS) / 4; i += NTHREADS)
        s4[i] = tg4[i];
    __syncthreads();

    float c   = 0.0f;
    int   cnt = 0;

    #pragma unroll
    for (int r = 0; r < RPB; r++) {
        const float4 o = (r == 0) ? o0 : (r == 1) ? o1 : (r == 2) ? o2 : o3;
        const float* q = s_tgt + r * ROW_FLOATS + t * 5;   // conflict-free: gcd(5,32)=1
        const float t0 = q[0], t1 = q[1], t2 = q[2], t3 = q[3], t4 = q[4];
        const float censor = 1.0f - (o.x + o.y + o.z + o.w);
        c += t0 * __logf(censor + EPSF)
           + t1 * __logf(o.x + EPSF)
           + t2 * __logf(o.y + EPSF)
           + t3 * __logf(o.z + EPSF)
           + t4 * __logf(o.w + EPSF);
        cnt += ((t0 + t1 + t2 + t3 + t4) > 0.0f);
    }

    // Warp reduction.
    #pragma unroll
    for (int off = 16; off > 0; off >>= 1) {
        c   += __shfl_down_sync(0xffffffffu, c, off);
        cnt += __shfl_down_sync(0xffffffffu, cnt, off);
    }
    if ((tid & 31) == 0) {
        s_sum[tid >> 5] = c;
        s_cnt[tid >> 5] = cnt;
    }
    __syncthreads();

    // Final reduce across 16 warps (lanes 0..15 of warp 0); all other warps
    // are done after this barrier and exit immediately.
    if (tid < NTHREADS / 32) {
        c   = s_sum[tid];
        cnt = s_cnt[tid];
        #pragma unroll
        for (int off = (NTHREADS / 64); off > 0; off >>= 1) {
            c   += __shfl_down_sync(0xffffu, c, off);
            cnt += __shfl_down_sync(0xffffu, cnt, off);
        }
        if (tid == 0) {
            // Fire-and-forget accumulation (relaxed REDs).
            atomicAdd(&g_loss, (double)c);
            atomicAdd(&g_count, (unsigned int)cnt);

            // Ticket with acq_rel: release publishes this block's REDs before
            // the increment; acquire on the winning increment synchronizes
            // with every other block's release -> their REDs are visible.
            unsigned int tk;
            asm volatile("atom.acq_rel.gpu.global.add.u32 %0, [%1], %2;"
                         : "=r"(tk)
                         : "l"(&g_ticket), "r"(1u)
                         : "memory");

            if (tk == (unsigned int)(nblocks - 1)) {
                const double loss       = *((volatile double*)&g_loss);
                const unsigned int ct   = *((volatile unsigned int*)&g_count);
                out[0] = (ct > 0u) ? (float)(-loss / (double)ct) : 0.0f;
                // Reset for the next graph replay (no other block is active).
                g_loss   = 0.0;
                g_count  = 0u;
                *((volatile unsigned int*)&g_ticket) = 0u;
            }
        }
    }
}

extern "C" void kernel_launch(void* const* d_in, const int* in_sizes, int n_in,
                              void* d_out, int out_size)
{
    const float* outputs = (const float*)d_in[0];
    const float* targets = (const float*)d_in[1];
    float* out = (float*)d_out;

    const int B       = in_sizes[1] / ROW_FLOATS;  // 16384
    const int nblocks = B / RPB;                   // 4096

    cl_main_kernel<<<nblocks, NTHREADS>>>(outputs, targets, out, nblocks);
}

// round 11
// speedup vs baseline: 1.0007x; 1.0007x over previous
#include <cuda_runtime.h>
#include <cuda_bf16.h>

// CensoredLoss: outputs [B, T, V-1] f32, targets [B, T, V] f32, T=512, V=5.
// loss  = sum_{b,t} [ tgt0*log(1 - sum(out) + EPS) + sum_v tgt_{v+1}*log(out_v + EPS) ]
//         (masked rows have all-zero targets -> contribute exactly 0)
// count = #{(b,t) : sum_v targets[b,t,v] > 0}   (valid prefix => sum of lengths)
// result = count > 0 ? -loss/count : 0
//
// SINGLE kernel, grid = nblocks+1.
//   blocks 0..nblocks-1: 4 rows each, smem-staged targets, block reduction,
//     then THREE fire-and-forget REDs: loss, count, and a red.release ticket
//     (release orders the first two; no return value -> CTA retires with no
//     L2 round-trip wait, unlike the R10 acq_rel ticket).
//   block nblocks (scheduled last): thread 0 spin-polls the ticket with
//     ld.acquire.gpu; on observing nblocks it has acquired every block's
//     REDs, writes out[0], and resets the accumulators for the next replay.

#define T_DIM 512
#define V_DIM 5
#define RPB   4                       // rows per worker block
#define ROW_FLOATS (T_DIM * V_DIM)    // 2560
#define EPSF  1e-8f
#define NTHREADS 512

__device__ double       g_loss;       // zero at module load; finalizer re-zeros
__device__ unsigned int g_count;
__device__ unsigned int g_ticket;

__global__ __launch_bounds__(NTHREADS, 4)
void cl_main_kernel(const float* __restrict__ outputs,
                    const float* __restrict__ targets,
                    float* __restrict__ out,
                    int nblocks)
{
    __shared__ float s_tgt[RPB * ROW_FLOATS];      // 40960 B, four rows of targets
    __shared__ float s_sum[NTHREADS / 32];
    __shared__ int   s_cnt[NTHREADS / 32];

    const int tid = threadIdx.x;

    // ---- Finalizer block (last in the grid, scheduled in the last wave) ----
    if (blockIdx.x == (unsigned)nblocks) {
        if (tid == 0) {
            unsigned int tk;
            for (;;) {
                asm volatile("ld.acquire.gpu.global.u32 %0, [%1];"
                             : "=r"(tk) : "l"(&g_ticket) : "memory");
                if (tk >= (unsigned int)nblocks) break;
                __nanosleep(256);
            }
            // Acquire above synchronizes-with every worker's red.release:
            // all loss/count REDs are visible now.
            const double loss     = *((volatile double*)&g_loss);
            const unsigned int ct = *((volatile unsigned int*)&g_count);
            out[0] = (ct > 0u) ? (float)(-loss / (double)ct) : 0.0f;
            // Reset for the next graph replay (all workers retired).
            g_loss  = 0.0;
            g_count = 0u;
            *((volatile unsigned int*)&g_ticket) = 0u;
        }
        return;   // other 511 threads exit immediately (no barrier in this block)
    }

    // ---- Worker blocks ----
    const int b0 = blockIdx.x * RPB;
    const int t  = tid;                             // one timestep per thread per row

    // Prefetch all four rows' outputs records (float4, 16B aligned) first so
    // their DRAM latency overlaps the targets staging.
    const float4* og4 = reinterpret_cast<const float4*>(outputs);
    const float4 o0 = og4[(size_t)(b0 + 0) * T_DIM + t];
    const float4 o1 = og4[(size_t)(b0 + 1) * T_DIM + t];
    const float4 o2 = og4[(size_t)(b0 + 2) * T_DIM + t];
    const float4 o3 = og4[(size_t)(b0 + 3) * T_DIM + t];

    // Stage 4 rows of targets via fully-coalesced float4 loads (rows adjacent;
    // block base = b0 * 2560 floats = b0 * 10240 B -> 16B aligned).
    const float4* tg4 = reinterpret_cast<const float4*>(
        targets + (size_t)b0 * ROW_FLOATS);
    float4* s4 = reinterpret_cast<float4*>(s_tgt);
    #pragma unroll
    for (int i = tid; i < (RPB * ROW_FLOATS) / 4; i += NTHREADS)
        s4[i] = tg4[i];
    __syncthreads();

    float c   = 0.0f;
    int   cnt = 0;

    #pragma unroll
    for (int r = 0; r < RPB; r++) {
        const float4 o = (r == 0) ? o0 : (r == 1) ? o1 : (r == 2) ? o2 : o3;
        const float* q = s_tgt + r * ROW_FLOATS + t * 5;   // conflict-free: gcd(5,32)=1
        const float t0 = q[0], t1 = q[1], t2 = q[2], t3 = q[3], t4 = q[4];
        const float censor = 1.0f - (o.x + o.y + o.z + o.w);
        c += t0 * __logf(censor + EPSF)
           + t1 * __logf(o.x + EPSF)
           + t2 * __logf(o.y + EPSF)
           + t3 * __logf(o.z + EPSF)
           + t4 * __logf(o.w + EPSF);
        cnt += ((t0 + t1 + t2 + t3 + t4) > 0.0f);
    }

    // Warp reduction.
    #pragma unroll
    for (int off = 16; off > 0; off >>= 1) {
        c   += __shfl_down_sync(0xffffffffu, c, off);
        cnt += __shfl_down_sync(0xffffffffu, cnt, off);
    }
    if ((tid & 31) == 0) {
        s_sum[tid >> 5] = c;
        s_cnt[tid >> 5] = cnt;
    }
    __syncthreads();

    // Final reduce across 16 warps (lanes 0..15 of warp 0), then three
    // fire-and-forget REDs (no return values -> no round-trip wait; the
    // release on the ticket orders the loss/count REDs before it).
    if (tid < NTHREADS / 32) {
        c   = s_sum[tid];
        cnt = s_cnt[tid];
        #pragma unroll
        for (int off = (NTHREADS / 64); off > 0; off >>= 1) {
            c   += __shfl_down_sync(0xffffu, c, off);
            cnt += __shfl_down_sync(0xffffu, cnt, off);
        }
        if (tid == 0) {
            atomicAdd(&g_loss, (double)c);          // RED.f64 (return unused)
            atomicAdd(&g_count, (unsigned int)cnt); // RED.u32 (return unused)
            asm volatile("red.release.gpu.global.add.u32 [%0], %1;"
                         :: "l"(&g_ticket), "r"(1u) : "memory");
        }
    }
}

extern "C" void kernel_launch(void* const* d_in, const int* in_sizes, int n_in,
                              void* d_out, int out_size)
{
    const float* outputs = (const float*)d_in[0];
    const float* targets = (const float*)d_in[1];
    float* out = (float*)d_out;

    const int B       = in_sizes[1] / ROW_FLOATS;  // 16384
    const int nblocks = B / RPB;                   // 4096 worker blocks

    cl_main_kernel<<<nblocks + 1, NTHREADS>>>(outputs, targets, out, nblocks);
}

// round 12
// speedup vs baseline: 1.0105x; 1.0099x over previous
#include <cuda_runtime.h>
#include <cuda_bf16.h>
#include <cuda_pipeline.h>

// CensoredLoss: outputs [B, T, V-1] f32, targets [B, T, V] f32, T=512, V=5.
// loss  = sum_{b,t} [ tgt0*log(1 - sum(out) + EPS) + sum_v tgt_{v+1}*log(out_v + EPS) ]
//         (masked rows have all-zero targets -> contribute exactly 0)
// count = #{(b,t) : sum_v targets[b,t,v] > 0}
// result = count > 0 ? -loss/count : 0
//
// SINGLE kernel, grid = nblocks+1, 256-thread blocks, 2 rows/block:
//   - targets staged to smem via cp.async (no register round-trip),
//   - outputs read as 4 float4s/thread,
//   - 8 CTAs/SM for latency hiding; half-width barriers,
//   - workers end with fire-and-forget REDs + red.release ticket,
//   - finalizer block spin-acquires the ticket, writes out[0], resets state.

#define T_DIM 512
#define V_DIM 5
#define RPB   2                           // rows per worker block
#define ROW_FLOATS (T_DIM * V_DIM)        // 2560
#define EPSF  1e-8f
#define NTHREADS 256

__device__ double       g_loss;           // zero at module load; finalizer re-zeros
__device__ unsigned int g_count;
__device__ unsigned int g_ticket;

__global__ __launch_bounds__(NTHREADS, 8)
void cl_main_kernel(const float* __restrict__ outputs,
                    const float* __restrict__ targets,
                    float* __restrict__ out,
                    int nblocks)
{
    __shared__ float s_tgt[RPB * ROW_FLOATS];     // 20480 B, two rows of targets
    __shared__ float s_sum[NTHREADS / 32];
    __shared__ int   s_cnt[NTHREADS / 32];

    const int tid = threadIdx.x;

    // ---- Finalizer block (last in the grid, scheduled in the last wave) ----
    if (blockIdx.x == (unsigned)nblocks) {
        if (tid == 0) {
            unsigned int tk;
            for (;;) {
                asm volatile("ld.acquire.gpu.global.u32 %0, [%1];"
                             : "=r"(tk) : "l"(&g_ticket) : "memory");
                if (tk >= (unsigned int)nblocks) break;
                __nanosleep(128);
            }
            // Acquire synchronizes-with every worker's red.release.
            const double loss     = *((volatile double*)&g_loss);
            const unsigned int ct = *((volatile unsigned int*)&g_count);
            out[0] = (ct > 0u) ? (float)(-loss / (double)ct) : 0.0f;
            g_loss  = 0.0;
            g_count = 0u;
            *((volatile unsigned int*)&g_ticket) = 0u;
        }
        return;    // other threads exit immediately (no barrier in this block)
    }

    // ---- Worker blocks ----
    const int b0 = blockIdx.x * RPB;

    // Stage 2 rows of targets via cp.async (LDGSTS: no register round-trip,
    // keeps the front LDG batch small). 1280 float4s / 256 threads = 5 each.
    {
        const float4* src = reinterpret_cast<const float4*>(
            targets + (size_t)b0 * ROW_FLOATS);
        float4* dst = reinterpret_cast<float4*>(s_tgt);
        #pragma unroll
        for (int i = tid; i < (RPB * ROW_FLOATS) / 4; i += NTHREADS)
            __pipeline_memcpy_async(&dst[i], &src[i], 16);
        __pipeline_commit();
    }

    // Each thread covers 4 records: rows b0,b0+1 at timesteps tid, tid+256.
    // Issue all 4 output float4 loads while cp.async streams in the targets.
    const float4* og4 = reinterpret_cast<const float4*>(outputs);
    const float4 o00 = og4[(size_t)(b0 + 0) * T_DIM + tid];
    const float4 o01 = og4[(size_t)(b0 + 0) * T_DIM + tid + 256];
    const float4 o10 = og4[(size_t)(b0 + 1) * T_DIM + tid];
    const float4 o11 = og4[(size_t)(b0 + 1) * T_DIM + tid + 256];

    __pipeline_wait_prior(0);
    __syncthreads();

    float c   = 0.0f;
    int   cnt = 0;

    #pragma unroll
    for (int r = 0; r < RPB; r++) {
        #pragma unroll
        for (int k = 0; k < 2; k++) {
            const int t = tid + k * 256;
            const float4 o = (r == 0) ? (k == 0 ? o00 : o01)
                                      : (k == 0 ? o10 : o11);
            const float* q = s_tgt + r * ROW_FLOATS + t * 5;  // gcd(5,32)=1: conflict-free
            const float t0 = q[0], t1 = q[1], t2 = q[2], t3 = q[3], t4 = q[4];
            const float censor = 1.0f - (o.x + o.y + o.z + o.w);
            c += t0 * __logf(censor + EPSF)
               + t1 * __logf(o.x + EPSF)
               + t2 * __logf(o.y + EPSF)
               + t3 * __logf(o.z + EPSF)
               + t4 * __logf(o.w + EPSF);
            cnt += ((t0 + t1 + t2 + t3 + t4) > 0.0f);
        }
    }

    // Warp reduction.
    #pragma unroll
    for (int off = 16; off > 0; off >>= 1) {
        c   += __shfl_down_sync(0xffffffffu, c, off);
        cnt += __shfl_down_sync(0xffffffffu, cnt, off);
    }
    if ((tid & 31) == 0) {
        s_sum[tid >> 5] = c;
        s_cnt[tid >> 5] = cnt;
    }
    __syncthreads();

    // Final reduce across 8 warps (lanes 0..7 of warp 0), then fire-and-forget
    // REDs; the red.release ticket orders them for the finalizer's acquire.
    if (tid < NTHREADS / 32) {
        c   = s_sum[tid];
        cnt = s_cnt[tid];
        #pragma unroll
        for (int off = (NTHREADS / 64); off > 0; off >>= 1) {
            c   += __shfl_down_sync(0xffu, c, off);
            cnt += __shfl_down_sync(0xffu, cnt, off);
        }
        if (tid == 0) {
            atomicAdd(&g_loss, (double)c);           // RED.f64 (return unused)
            atomicAdd(&g_count, (unsigned int)cnt);  // RED.u32 (return unused)
            asm volatile("red.release.gpu.global.add.u32 [%0], %1;"
                         :: "l"(&g_ticket), "r"(1u) : "memory");
        }
    }
}

extern "C" void kernel_launch(void* const* d_in, const int* in_sizes, int n_in,
                              void* d_out, int out_size)
{
    const float* outputs = (const float*)d_in[0];
    const float* targets = (const float*)d_in[1];
    float* out = (float*)d_out;

    const int B       = in_sizes[1] / ROW_FLOATS;   // 16384
    const int nblocks = B / RPB;                    // 8192 worker blocks

    cl_main_kernel<<<nblocks + 1, NTHREADS>>>(outputs, targets, out, nblocks);
}

// round 13
// speedup vs baseline: 1.1426x; 1.1308x over previous
#include <cuda_runtime.h>
#include <cuda_bf16.h>
#include <cuda_pipeline.h>

// CensoredLoss: outputs [B, T, V-1] f32, targets [B, T, V] f32, T=512, V=5.
// loss  = sum_{b,t} [ tgt0*log(1 - sum(out) + EPS) + sum_v tgt_{v+1}*log(out_v + EPS) ]
//         (masked rows have all-zero targets -> contribute exactly 0)
// count = #{(b,t) : sum_v targets[b,t,v] > 0}
// result = count > 0 ? -loss/count : 0
//
// KEY: ~50% of records are masked (uniform lengths 1..512). Masked records
// need no outputs data at all -> load outputs CONDITIONALLY on per_t > 0.
// Cuts DRAM traffic 302 MB -> ~235 MB. Valid records are a row prefix, so
// the skip is warp-coherent except one boundary warp per row.
//
// SINGLE kernel, grid = nblocks+1, 256-thread blocks, 2 rows/block:
//   targets staged via cp.async; conditional float4 outputs loads;
//   workers end with fire-and-forget REDs + red.release ticket;
//   finalizer block spin-acquires, writes out[0], resets state.

#define T_DIM 512
#define V_DIM 5
#define RPB   2                           // rows per worker block
#define ROW_FLOATS (T_DIM * V_DIM)        // 2560
#define EPSF  1e-8f
#define NTHREADS 256

__device__ double       g_loss;           // zero at module load; finalizer re-zeros
__device__ unsigned int g_count;
__device__ unsigned int g_ticket;

__global__ __launch_bounds__(NTHREADS, 8)
void cl_main_kernel(const float* __restrict__ outputs,
                    const float* __restrict__ targets,
                    float* __restrict__ out,
                    int nblocks)
{
    __shared__ float s_tgt[RPB * ROW_FLOATS];     // 20480 B, two rows of targets
    __shared__ float s_sum[NTHREADS / 32];
    __shared__ int   s_cnt[NTHREADS / 32];

    const int tid = threadIdx.x;

    // ---- Finalizer block (last in the grid, scheduled in the last wave) ----
    if (blockIdx.x == (unsigned)nblocks) {
        if (tid == 0) {
            unsigned int tk;
            for (;;) {
                asm volatile("ld.acquire.gpu.global.u32 %0, [%1];"
                             : "=r"(tk) : "l"(&g_ticket) : "memory");
                if (tk >= (unsigned int)nblocks) break;
                __nanosleep(128);
            }
            // Acquire synchronizes-with every worker's red.release.
            const double loss     = *((volatile double*)&g_loss);
            const unsigned int ct = *((volatile unsigned int*)&g_count);
            out[0] = (ct > 0u) ? (float)(-loss / (double)ct) : 0.0f;
            g_loss  = 0.0;
            g_count = 0u;
            *((volatile unsigned int*)&g_ticket) = 0u;
        }
        return;    // other threads exit immediately (no barrier in this block)
    }

    // ---- Worker blocks ----
    const int b0 = blockIdx.x * RPB;

    // Stage 2 rows of targets via cp.async (no register round-trip).
    {
        const float4* src = reinterpret_cast<const float4*>(
            targets + (size_t)b0 * ROW_FLOATS);
        float4* dst = reinterpret_cast<float4*>(s_tgt);
        #pragma unroll
        for (int i = tid; i < (RPB * ROW_FLOATS) / 4; i += NTHREADS)
            __pipeline_memcpy_async(&dst[i], &src[i], 16);
        __pipeline_commit();
    }
    __pipeline_wait_prior(0);
    __syncthreads();

    const float4* og4 = reinterpret_cast<const float4*>(outputs);
    float c   = 0.0f;
    int   cnt = 0;

    // Each thread covers 4 records: rows b0, b0+1 at timesteps tid, tid+256.
    #pragma unroll
    for (int r = 0; r < RPB; r++) {
        #pragma unroll
        for (int k = 0; k < 2; k++) {
            const int t = tid + k * 256;
            const float* q = s_tgt + r * ROW_FLOATS + t * 5;  // gcd(5,32)=1: conflict-free
            const float t0 = q[0], t1 = q[1], t2 = q[2], t3 = q[3], t4 = q[4];
            const int nz = ((t0 + t1 + t2 + t3 + t4) > 0.0f);
            cnt += nz;
            if (nz) {
                // Only valid records touch outputs (saves ~50% of that stream).
                const float4 o = og4[(size_t)(b0 + r) * T_DIM + t];
                const float censor = 1.0f - (o.x + o.y + o.z + o.w);
                c += t0 * __logf(censor + EPSF)
                   + t1 * __logf(o.x + EPSF)
                   + t2 * __logf(o.y + EPSF)
                   + t3 * __logf(o.z + EPSF)
                   + t4 * __logf(o.w + EPSF);
            }
        }
    }

    // Warp reduction.
    #pragma unroll
    for (int off = 16; off > 0; off >>= 1) {
        c   += __shfl_down_sync(0xffffffffu, c, off);
        cnt += __shfl_down_sync(0xffffffffu, cnt, off);
    }
    if ((tid & 31) == 0) {
        s_sum[tid >> 5] = c;
        s_cnt[tid >> 5] = cnt;
    }
    __syncthreads();

    // Final reduce across 8 warps (lanes 0..7 of warp 0), then fire-and-forget
    // REDs; the red.release ticket orders them for the finalizer's acquire.
    if (tid < NTHREADS / 32) {
        c   = s_sum[tid];
        cnt = s_cnt[tid];
        #pragma unroll
        for (int off = (NTHREADS / 64); off > 0; off >>= 1) {
            c   += __shfl_down_sync(0xffu, c, off);
            cnt += __shfl_down_sync(0xffu, cnt, off);
        }
        if (tid == 0) {
            atomicAdd(&g_loss, (double)c);           // RED.f64 (return unused)
            atomicAdd(&g_count, (unsigned int)cnt);  // RED.u32 (return unused)
            asm volatile("red.release.gpu.global.add.u32 [%0], %1;"
                         :: "l"(&g_ticket), "r"(1u) : "memory");
        }
    }
}

extern "C" void kernel_launch(void* const* d_in, const int* in_sizes, int n_in,
                              void* d_out, int out_size)
{
    const float* outputs = (const float*)d_in[0];
    const float* targets = (const float*)d_in[1];
    float* out = (float*)d_out;

    const int B       = in_sizes[1] / ROW_FLOATS;   // 16384
    const int nblocks = B / RPB;                    // 8192 worker blocks

    cl_main_kernel<<<nblocks + 1, NTHREADS>>>(outputs, targets, out, nblocks);
}